// round 6
// baseline (speedup 1.0000x reference)
#include <cuda_runtime.h>
#include <cuda_bf16.h>
#include <cstdint>

// StatsQuantizer forward, fused single-pass.
//   sf[r] = sum(|W[r,:]|)/4096 ;  out = sf*(rint(clamp(W/sf,lo,hi)*8-0.5)+0.5)/8
//
// R3: 2 rows per CTA, software-pipelined. Row-B loads are issued before
// row-A's reduction barrier + store phase, keeping read and write streams
// simultaneously in flight per CTA (steadier DRAM R/W mix, fewer barriers
// per byte). 512 threads, 4 float4 per row per thread, double-buffered.

#define ROW_LEN   8192
#define THREADS   512
#define V4_PER_T  4          // 8192 / 4 / 512

__global__ __launch_bounds__(THREADS, 2)
void statsquant_kernel(const float* __restrict__ w,
                       const float* __restrict__ clip_val,
                       float* __restrict__ out)
{
    const size_t baseA = (size_t)(2 * blockIdx.x) * ROW_LEN;
    const size_t baseB = baseA + ROW_LEN;
    const float4* __restrict__ wA = reinterpret_cast<const float4*>(w + baseA);
    const float4* __restrict__ wB = reinterpret_cast<const float4*>(w + baseB);
    float4* __restrict__ oA = reinterpret_cast<float4*>(out + baseA);
    float4* __restrict__ oB = reinterpret_cast<float4*>(out + baseB);

    const int t = threadIdx.x;

    __shared__ float redA[16];
    __shared__ float redB[16];
    __shared__ float totA, totB;

    // ---- Load row A, accumulate |.| ----
    float4 vA[V4_PER_T];
    float sA = 0.0f;
#pragma unroll
    for (int i = 0; i < V4_PER_T; ++i) {
        vA[i] = __ldcs(&wA[t + i * THREADS]);
        sA += fabsf(vA[i].x) + fabsf(vA[i].y) + fabsf(vA[i].z) + fabsf(vA[i].w);
    }

    // ---- Issue row B loads NOW (independent; in flight across A's barrier
    //      and store phase) ----
    float4 vB[V4_PER_T];
#pragma unroll
    for (int i = 0; i < V4_PER_T; ++i)
        vB[i] = __ldcs(&wB[t + i * THREADS]);

    // ---- Reduce A ----
#pragma unroll
    for (int o = 16; o > 0; o >>= 1)
        sA += __shfl_xor_sync(0xffffffffu, sA, o);
    if ((t & 31) == 0) redA[t >> 5] = sA;
    __syncthreads();
    if (t < 32) {
        float r = (t < 16) ? redA[t] : 0.0f;
#pragma unroll
        for (int o = 8; o > 0; o >>= 1)
            r += __shfl_xor_sync(0xffffffffu, r, o);
        if (t == 0) totA = r;
    }
    __syncthreads();

    const float hc = 0.5f * clip_val[0];
    const float lo = -hc;
    const float hi = hc - 1e-6f;

    // ---- Quantize + store row A (row-B loads still landing meanwhile) ----
    {
        const float sf     = totA * (1.0f / 4096.0f);
        const float inv_sf = 1.0f / sf;
        const float osc    = sf * 0.125f;
#pragma unroll
        for (int i = 0; i < V4_PER_T; ++i) {
            float4 q;
            float c;
            c = fminf(fmaxf(vA[i].x * inv_sf, lo), hi);
            q.x = (rintf(fmaf(c, 8.0f, -0.5f)) + 0.5f) * osc;
            c = fminf(fmaxf(vA[i].y * inv_sf, lo), hi);
            q.y = (rintf(fmaf(c, 8.0f, -0.5f)) + 0.5f) * osc;
            c = fminf(fmaxf(vA[i].z * inv_sf, lo), hi);
            q.z = (rintf(fmaf(c, 8.0f, -0.5f)) + 0.5f) * osc;
            c = fminf(fmaxf(vA[i].w * inv_sf, lo), hi);
            q.w = (rintf(fmaf(c, 8.0f, -0.5f)) + 0.5f) * osc;
            __stcs(&oA[t + i * THREADS], q);
        }
    }

    // ---- Accumulate + reduce B ----
    float sB = 0.0f;
#pragma unroll
    for (int i = 0; i < V4_PER_T; ++i)
        sB += fabsf(vB[i].x) + fabsf(vB[i].y) + fabsf(vB[i].z) + fabsf(vB[i].w);
#pragma unroll
    for (int o = 16; o > 0; o >>= 1)
        sB += __shfl_xor_sync(0xffffffffu, sB, o);
    if ((t & 31) == 0) redB[t >> 5] = sB;
    __syncthreads();
    if (t < 32) {
        float r = (t < 16) ? redB[t] : 0.0f;
#pragma unroll
        for (int o = 8; o > 0; o >>= 1)
            r += __shfl_xor_sync(0xffffffffu, r, o);
        if (t == 0) totB = r;
    }
    __syncthreads();

    // ---- Quantize + store row B ----
    {
        const float sf     = totB * (1.0f / 4096.0f);
        const float inv_sf = 1.0f / sf;
        const float osc    = sf * 0.125f;
#pragma unroll
        for (int i = 0; i < V4_PER_T; ++i) {
            float4 q;
            float c;
            c = fminf(fmaxf(vB[i].x * inv_sf, lo), hi);
            q.x = (rintf(fmaf(c, 8.0f, -0.5f)) + 0.5f) * osc;
            c = fminf(fmaxf(vB[i].y * inv_sf, lo), hi);
            q.y = (rintf(fmaf(c, 8.0f, -0.5f)) + 0.5f) * osc;
            c = fminf(fmaxf(vB[i].z * inv_sf, lo), hi);
            q.z = (rintf(fmaf(c, 8.0f, -0.5f)) + 0.5f) * osc;
            c = fminf(fmaxf(vB[i].w * inv_sf, lo), hi);
            q.w = (rintf(fmaf(c, 8.0f, -0.5f)) + 0.5f) * osc;
            __stcs(&oB[t + i * THREADS], q);
        }
    }
}

extern "C" void kernel_launch(void* const* d_in, const int* in_sizes, int n_in,
                              void* d_out, int out_size)
{
    const float* w    = (const float*)d_in[0];
    const float* clip = (const float*)d_in[1];
    float* out        = (float*)d_out;
    (void)in_sizes; (void)n_in; (void)out_size;

    statsquant_kernel<<<ROW_LEN / 2, THREADS>>>(w, clip, out);
}